// round 5
// baseline (speedup 1.0000x reference)
#include <cuda_runtime.h>
#include <cuda_bf16.h>
#include <cstdint>

#define BATCH 8
#define SEQ   2048
#define DIM   128
#define INV_TEMP 0.08838834764831843f

typedef unsigned long long ull;

// ---------------- device scratch ----------------
__device__ float g_inv_rs[BATCH * SEQ];
__device__ __align__(16) __nv_bfloat16 g_qhi[BATCH * SEQ * DIM];
__device__ __align__(16) __nv_bfloat16 g_qlo[BATCH * SEQ * DIM];
__device__ __align__(16) __nv_bfloat16 g_vhi[BATCH * SEQ * DIM];
__device__ __align__(16) __nv_bfloat16 g_vlo[BATCH * SEQ * DIM];

// ---------------- cp.async ----------------
__device__ __forceinline__ void cp_async16(uint32_t smem_dst, const void* gsrc) {
    asm volatile("cp.async.ca.shared.global [%0], [%1], 16;\n"
                 :: "r"(smem_dst), "l"(gsrc));
}
#define CP_COMMIT() asm volatile("cp.async.commit_group;\n" ::: "memory")
#define CP_WAIT0()  asm volatile("cp.async.wait_group 0;\n" ::: "memory")
#define CP_WAIT1()  asm volatile("cp.async.wait_group 1;\n" ::: "memory")

__device__ __forceinline__ uint32_t smem_u32(const void* p) {
    uint32_t a;
    asm("{ .reg .u64 t; cvta.to.shared.u64 t, %1; cvt.u32.u64 %0, t; }"
        : "=r"(a) : "l"(p));
    return a;
}

// ---------------- mma / ldmatrix ----------------
__device__ __forceinline__ void ldm4(unsigned* r, uint32_t addr) {
    asm volatile("ldmatrix.sync.aligned.m8n8.x4.shared.b16 {%0,%1,%2,%3}, [%4];"
                 : "=r"(r[0]), "=r"(r[1]), "=r"(r[2]), "=r"(r[3]) : "r"(addr));
}
__device__ __forceinline__ void mma16816(float* d, const unsigned* a,
                                         const unsigned* b) {
    asm volatile(
        "mma.sync.aligned.m16n8k16.row.col.f32.bf16.bf16.f32 "
        "{%0,%1,%2,%3}, {%4,%5,%6,%7}, {%8,%9}, {%0,%1,%2,%3};"
        : "+f"(d[0]), "+f"(d[1]), "+f"(d[2]), "+f"(d[3])
        : "r"(a[0]), "r"(a[1]), "r"(a[2]), "r"(a[3]), "r"(b[0]), "r"(b[1]));
}

// =====================================================================
// split kernel: q,v -> bf16 hi/lo
// =====================================================================
__global__ void __launch_bounds__(256)
split_kernel(const float* __restrict__ q, const float* __restrict__ v) {
    int i = (blockIdx.x * 256 + threadIdx.x) * 4;
    float4 fq = *(const float4*)(q + i);
    float4 fv = *(const float4*)(v + i);
    float xq[4] = {fq.x, fq.y, fq.z, fq.w};
    float xv[4] = {fv.x, fv.y, fv.z, fv.w};
    __nv_bfloat16 qh[4], ql[4], vh[4], vl[4];
#pragma unroll
    for (int j = 0; j < 4; ++j) {
        qh[j] = __float2bfloat16(xq[j]);
        ql[j] = __float2bfloat16(xq[j] - __bfloat162float(qh[j]));
        vh[j] = __float2bfloat16(xv[j]);
        vl[j] = __float2bfloat16(xv[j] - __bfloat162float(vh[j]));
    }
    *(ull*)(g_qhi + i) = *(ull*)qh;
    *(ull*)(g_qlo + i) = *(ull*)ql;
    *(ull*)(g_vhi + i) = *(ull*)vh;
    *(ull*)(g_vlo + i) = *(ull*)vl;
}

// =====================================================================
// Pass 1 (mma.sync bf16 split): u = exp(q.v^T / sqrt(D)); inv rowsums.
// CTA: 128 i-rows, 256 thr (8 warps: 4m x 2n, warp tile 32x64).
// smem: Qlo tile (persistent) + double-buffered Vhi/Vlo tiles, pitch 272B.
// =====================================================================
#define PITCH 272                         // bytes per row (136 bf16)
#define TILE_B (128 * PITCH)              // 34816
#define OFF_QLO   0
#define OFF_VBUF(x) (TILE_B + (x) * (2 * TILE_B))   // vhi at +0, vlo at +TILE_B
#define OFF_RS    (TILE_B + 4 * TILE_B)             // 174080
#define P1_SMEM   (OFF_RS + 128 * 2 * 4)            // +1KB

// stage one 128x128 bf16 tile into padded smem
__device__ __forceinline__ void stage_tile(uint32_t dst,
                                           const __nv_bfloat16* src, int t) {
#pragma unroll
    for (int it = 0; it < 8; ++it) {
        int id = it * 256 + t;
        int r = id >> 4, c = id & 15;
        cp_async16(dst + r * PITCH + c * 16, src + r * 128 + c * 8);
    }
}

__global__ void __launch_bounds__(256, 1)
pass1_kernel(float* __restrict__ u) {
    extern __shared__ char sm[];
    const uint32_t smb = smem_u32(sm);
    float* rsbuf = (float*)(sm + OFF_RS);   // [128][2]

    const int b  = blockIdx.y;
    const int i0 = blockIdx.x * 128;
    const int t  = threadIdx.x;
    const int w  = t >> 5;
    const int l  = t & 31;
    const int wm = w & 3;        // warp m index (rows wm*32..+31)
    const int wn = w >> 2;       // warp n index (cols wn*64..+63)

    const __nv_bfloat16* qhg = g_qhi + ((size_t)b * SEQ + i0) * DIM;
    const __nv_bfloat16* qlg = g_qlo + ((size_t)b * SEQ + i0) * DIM;
    const __nv_bfloat16* vhg = g_vhi + (size_t)b * SEQ * DIM;
    const __nv_bfloat16* vlg = g_vlo + (size_t)b * SEQ * DIM;

    // lane offsets for ldmatrix address patterns
    const int rA = (l & 7) + ((l >> 3) & 1) * 8;   // A: row within 16
    const int cA = (l >> 4) * 8;                   // A: col offset
    const int rB = (l & 7) + (l >> 4) * 8;         // B: row within 16
    const int cB = ((l >> 3) & 1) * 8;             // B: col offset

    // ---- prologue: stage Qhi (into vbuf0) + Qlo (persistent) ----
    stage_tile(smb + OFF_VBUF(0), qhg, t);
    stage_tile(smb + OFF_QLO,     qlg, t);
    CP_COMMIT();
    CP_WAIT0();
    __syncthreads();

    // ---- load Qhi fragments to registers ----
    unsigned qh[2][8][4];
#pragma unroll
    for (int f = 0; f < 2; ++f)
#pragma unroll
        for (int k8 = 0; k8 < 8; ++k8) {
            uint32_t addr = smb + OFF_VBUF(0) +
                (wm * 32 + f * 16 + rA) * PITCH + (k8 * 16 + cA) * 2;
            ldm4(qh[f][k8], addr);
        }
    __syncthreads();   // done reading staging area

    // Qlo ldmatrix bases (per m-frag)
    uint32_t qloA[2];
#pragma unroll
    for (int f = 0; f < 2; ++f)
        qloA[f] = smb + OFF_QLO + (wm * 32 + f * 16 + rA) * PITCH + cA * 2;

    // B ldmatrix row offsets per n-frag-pair p
    uint32_t bRow[4];
#pragma unroll
    for (int p = 0; p < 4; ++p)
        bRow[p] = (wn * 64 + p * 16 + rB) * PITCH + cB * 2;

    // ---- prefetch V chunks 0,1 ----
    stage_tile(smb + OFF_VBUF(0),          vhg, t);
    stage_tile(smb + OFF_VBUF(0) + TILE_B, vlg, t);
    CP_COMMIT();
    stage_tile(smb + OFF_VBUF(1),          vhg + 128 * DIM, t);
    stage_tile(smb + OFF_VBUF(1) + TILE_B, vlg + 128 * DIM, t);
    CP_COMMIT();

    // per-thread u output pointers
    float* up[2];
#pragma unroll
    for (int f = 0; f < 2; ++f)
        up[f] = u + ((size_t)(b * SEQ + i0 + wm * 32 + f * 16 + (l >> 2))) * SEQ
                  + wn * 64 + (l & 3) * 2;

    float rs[2][2] = {{0.f, 0.f}, {0.f, 0.f}};
    const int NCHUNK = SEQ / 128;

    for (int c = 0; c < NCHUNK; ++c) {
        CP_WAIT1();
        __syncthreads();   // chunk c visible to all

        const uint32_t vh = smb + OFF_VBUF(c & 1);
        const uint32_t vl = vh + TILE_B;

        float acc[2][8][4];
#pragma unroll
        for (int f = 0; f < 2; ++f)
#pragma unroll
            for (int n = 0; n < 8; ++n)
#pragma unroll
                for (int x = 0; x < 4; ++x) acc[f][n][x] = 0.0f;

#pragma unroll
        for (int k8 = 0; k8 < 8; ++k8) {
            unsigned bh[4][4];
#pragma unroll
            for (int p = 0; p < 4; ++p)
                ldm4(bh[p], vh + bRow[p] + k8 * 32);
            unsigned al[2][4];
            ldm4(al[0], qloA[0] + k8 * 32);
            ldm4(al[1], qloA[1] + k8 * 32);
#pragma unroll
            for (int p = 0; p < 4; ++p)
#pragma unroll
                for (int h = 0; h < 2; ++h) {
                    const unsigned* bb = &bh[p][2 * h];
                    int n = 2 * p + h;
                    mma16816(acc[0][n], qh[0][k8], bb);   // Qhi . Vhi
                    mma16816(acc[1][n], qh[1][k8], bb);
                    mma16816(acc[0][n], al[0], bb);       // Qlo . Vhi
                    mma16816(acc[1][n], al[1], bb);
                }
            unsigned bl[4][4];
#pragma unroll
            for (int p = 0; p < 4; ++p)
                ldm4(bl[p], vl + bRow[p] + k8 * 32);
#pragma unroll
            for (int p = 0; p < 4; ++p)
#pragma unroll
                for (int h = 0; h < 2; ++h) {
                    const unsigned* bb = &bl[p][2 * h];
                    int n = 2 * p + h;
                    mma16816(acc[0][n], qh[0][k8], bb);   // Qhi . Vlo
                    mma16816(acc[1][n], qh[1][k8], bb);
                }
        }

        __syncthreads();   // all warps done reading buf (c&1)

        if (c + 2 < NCHUNK) {
            const uint32_t nb = smb + OFF_VBUF(c & 1);
            stage_tile(nb,          vhg + (size_t)(c + 2) * 128 * DIM, t);
            stage_tile(nb + TILE_B, vlg + (size_t)(c + 2) * 128 * DIM, t);
        }
        CP_COMMIT();   // keep group count in lockstep even on tail chunks

        // ---- epilogue: exp + rowsum + store (register-resident) ----
#pragma unroll
        for (int f = 0; f < 2; ++f) {
            float* row0 = up[f] + c * 128;
            float* row1 = row0 + 8 * SEQ;
#pragma unroll
            for (int n = 0; n < 8; ++n) {
                float e0 = __expf(acc[f][n][0] * INV_TEMP);
                float e1 = __expf(acc[f][n][1] * INV_TEMP);
                float e2 = __expf(acc[f][n][2] * INV_TEMP);
                float e3 = __expf(acc[f][n][3] * INV_TEMP);
                rs[f][0] += e0 + e1;
                rs[f][1] += e2 + e3;
                *(float2*)(row0 + n * 8) = make_float2(e0, e1);
                *(float2*)(row1 + n * 8) = make_float2(e2, e3);
            }
        }
    }

    // ---- rowsums: quad-reduce, cross-warp combine via smem ----
#pragma unroll
    for (int f = 0; f < 2; ++f)
#pragma unroll
        for (int h = 0; h < 2; ++h) {
            rs[f][h] += __shfl_xor_sync(0xffffffffu, rs[f][h], 1);
            rs[f][h] += __shfl_xor_sync(0xffffffffu, rs[f][h], 2);
        }
    if ((l & 3) == 0) {
#pragma unroll
        for (int f = 0; f < 2; ++f)
#pragma unroll
            for (int h = 0; h < 2; ++h) {
                int row = wm * 32 + f * 16 + h * 8 + (l >> 2);
                rsbuf[row * 2 + wn] = rs[f][h];
            }
    }
    __syncthreads();
    if (t < 128)
        g_inv_rs[b * SEQ + i0 + t] = 1.0f / (rsbuf[t * 2] + rsbuf[t * 2 + 1]);
}

// =====================================================================
// Pass 2 (SIMT fp32, unchanged): attn = u * inv_rs (in place); out = attn^T v
// =====================================================================
__device__ __forceinline__ void fma2(ull& acc, ull a, ull bb) {
    asm("fma.rn.f32x2 %0, %1, %2, %0;" : "+l"(acc) : "l"(a), "l"(bb));
}
__device__ __forceinline__ ull pack2(float x, float y) {
    ull r; asm("mov.b64 %0, {%1, %2};" : "=l"(r) : "f"(x), "f"(y)); return r;
}
__device__ __forceinline__ float2 unpack2(ull v) {
    float2 f; asm("mov.b64 {%0, %1}, %2;" : "=f"(f.x), "=f"(f.y) : "l"(v)); return f;
}
__device__ __forceinline__ void cp_async16g(void* smem_dst, const void* gmem_src) {
    unsigned a = (unsigned)__cvta_generic_to_shared(smem_dst);
    asm volatile("cp.async.ca.shared.global [%0], [%1], 16;\n" :: "r"(a), "l"(gmem_src));
}

#define P2_UW 36

__global__ void __launch_bounds__(256)
pass2_kernel(const float* __restrict__ v, float* __restrict__ attn,
             float* __restrict__ out) {
    __shared__ __align__(16) float us[32][P2_UW];
    __shared__ __align__(16) float vsm[2][32][128];

    const int b  = blockIdx.y;
    const int j0 = blockIdx.x * 32;
    const int t  = threadIdx.x;
    const int tj = t & 15;
    const int td = t >> 4;
    const int ur = t >> 3;
    const int ug = t & 7;

    const float* vb  = v + (size_t)b * SEQ * DIM;
    float*       ab  = attn + (size_t)b * SEQ * SEQ;
    const float* irs = g_inv_rs + b * SEQ;
    float*       ob  = out + (size_t)b * SEQ * DIM;

#pragma unroll
    for (int it = 0; it < 4; ++it) {
        int idx = it * 256 + t;
        int i = idx >> 5, cg = idx & 31;
        cp_async16g(&vsm[0][i][cg * 4], vb + (size_t)i * DIM + cg * 4);
    }
    CP_COMMIT();
    float4 ureg = *(const float4*)(ab + (size_t)ur * SEQ + j0 + ug * 4);
    float  sreg = __ldg(irs + ur);

    ull acc[2][4];
#pragma unroll
    for (int jj = 0; jj < 2; ++jj)
#pragma unroll
        for (int p = 0; p < 4; ++p) acc[jj][p] = 0ull;

    for (int ic = 0; ic < SEQ / 32; ++ic) {
        const int i0 = ic * 32;
        float4 un = ureg;
        un.x *= sreg; un.y *= sreg; un.z *= sreg; un.w *= sreg;
        *(float4*)(ab + (size_t)(i0 + ur) * SEQ + j0 + ug * 4) = un;

        CP_WAIT0();
        __syncthreads();
        *(float4*)(&us[ur][ug * 4]) = un;

        if (ic + 1 < SEQ / 32) {
            const float* vsrc = vb + (size_t)(i0 + 32) * DIM;
            float* vdst = &vsm[(ic + 1) & 1][0][0];
#pragma unroll
            for (int it = 0; it < 4; ++it) {
                int idx = it * 256 + t;
                int i = idx >> 5, cg = idx & 31;
                cp_async16g(vdst + i * 128 + cg * 4, vsrc + (size_t)i * DIM + cg * 4);
            }
            CP_COMMIT();
            ureg = *(const float4*)(ab + (size_t)(i0 + 32 + ur) * SEQ + j0 + ug * 4);
            sreg = __ldg(irs + i0 + 32 + ur);
        }
        __syncthreads();

        const float (*vsb)[128] = vsm[ic & 1];
#pragma unroll 8
        for (int i = 0; i < 32; ++i) {
            float2 a = *(const float2*)(&us[i][tj * 2]);
            ull a0 = pack2(a.x, a.x);
            ull a1 = pack2(a.y, a.y);
            const ull* bp = (const ull*)(&vsb[i][td * 8]);
            ull b0 = bp[0], b1 = bp[1], b2 = bp[2], b3 = bp[3];
            fma2(acc[0][0], a0, b0); fma2(acc[0][1], a0, b1);
            fma2(acc[0][2], a0, b2); fma2(acc[0][3], a0, b3);
            fma2(acc[1][0], a1, b0); fma2(acc[1][1], a1, b1);
            fma2(acc[1][2], a1, b2); fma2(acc[1][3], a1, b3);
        }
    }

#pragma unroll
    for (int jj = 0; jj < 2; ++jj) {
        float2 o0 = unpack2(acc[jj][0]);
        float2 o1 = unpack2(acc[jj][1]);
        float2 o2 = unpack2(acc[jj][2]);
        float2 o3 = unpack2(acc[jj][3]);
        float* r = ob + (size_t)(j0 + tj * 2 + jj) * DIM + td * 8;
        *(float4*)(r)     = make_float4(o0.x, o0.y, o1.x, o1.y);
        *(float4*)(r + 4) = make_float4(o2.x, o2.y, o3.x, o3.y);
    }
}

// =====================================================================
extern "C" void kernel_launch(void* const* d_in, const int* in_sizes, int n_in,
                              void* d_out, int out_size) {
    const float* q = (const float*)d_in[0];
    // d_in[1] (k) unused by the reference
    const float* v = (const float*)d_in[2];

    float* out  = (float*)d_out;                      // [8,2048,128]
    float* attn = out + (size_t)BATCH * SEQ * DIM;    // [8,2048,2048]

    cudaFuncSetAttribute(pass1_kernel,
                         cudaFuncAttributeMaxDynamicSharedMemorySize, P1_SMEM);

    split_kernel<<<(BATCH * SEQ * DIM) / (256 * 4), 256>>>(q, v);

    dim3 g1(SEQ / 128, BATCH);
    pass1_kernel<<<g1, 256, P1_SMEM>>>(attn);

    dim3 g2(SEQ / 32, BATCH);
    pass2_kernel<<<g2, 256>>>(v, attn, out);
}

// round 6
// speedup vs baseline: 1.5494x; 1.5494x over previous
#include <cuda_runtime.h>
#include <cuda_bf16.h>
#include <cstdint>

#define BATCH 8
#define SEQ   2048
#define DIM   128
#define INV_TEMP 0.08838834764831843f

typedef unsigned long long ull;

// ---------------- device scratch ----------------
__device__ float g_inv_rs[BATCH * SEQ];
__device__ __align__(16) __nv_bfloat16 g_qhi[BATCH * SEQ * DIM];
__device__ __align__(16) __nv_bfloat16 g_qlo[BATCH * SEQ * DIM];
__device__ __align__(16) __nv_bfloat16 g_vhi[BATCH * SEQ * DIM];
__device__ __align__(16) __nv_bfloat16 g_vlo[BATCH * SEQ * DIM];

// ---------------- cp.async ----------------
__device__ __forceinline__ void cp_async16(uint32_t smem_dst, const void* gsrc) {
    asm volatile("cp.async.ca.shared.global [%0], [%1], 16;\n"
                 :: "r"(smem_dst), "l"(gsrc));
}
#define CP_COMMIT() asm volatile("cp.async.commit_group;\n" ::: "memory")
#define CP_WAIT0()  asm volatile("cp.async.wait_group 0;\n" ::: "memory")
#define CP_WAIT1()  asm volatile("cp.async.wait_group 1;\n" ::: "memory")

__device__ __forceinline__ uint32_t smem_u32(const void* p) {
    uint32_t a;
    asm("{ .reg .u64 t; cvta.to.shared.u64 t, %1; cvt.u32.u64 %0, t; }"
        : "=r"(a) : "l"(p));
    return a;
}

// ---------------- mma / ldmatrix ----------------
__device__ __forceinline__ void ldm4(unsigned* r, uint32_t addr) {
    asm volatile("ldmatrix.sync.aligned.m8n8.x4.shared.b16 {%0,%1,%2,%3}, [%4];"
                 : "=r"(r[0]), "=r"(r[1]), "=r"(r[2]), "=r"(r[3]) : "r"(addr));
}
__device__ __forceinline__ void ldm4t(unsigned* r, uint32_t addr) {
    asm volatile("ldmatrix.sync.aligned.m8n8.x4.trans.shared.b16 {%0,%1,%2,%3}, [%4];"
                 : "=r"(r[0]), "=r"(r[1]), "=r"(r[2]), "=r"(r[3]) : "r"(addr));
}
__device__ __forceinline__ void mma16816(float* d, const unsigned* a,
                                         const unsigned* b) {
    asm volatile(
        "mma.sync.aligned.m16n8k16.row.col.f32.bf16.bf16.f32 "
        "{%0,%1,%2,%3}, {%4,%5,%6,%7}, {%8,%9}, {%0,%1,%2,%3};"
        : "+f"(d[0]), "+f"(d[1]), "+f"(d[2]), "+f"(d[3])
        : "r"(a[0]), "r"(a[1]), "r"(a[2]), "r"(a[3]), "r"(b[0]), "r"(b[1]));
}

// =====================================================================
// split kernel: q,v -> bf16 hi/lo
// =====================================================================
__global__ void __launch_bounds__(256)
split_kernel(const float* __restrict__ q, const float* __restrict__ v) {
    int i = (blockIdx.x * 256 + threadIdx.x) * 4;
    float4 fq = *(const float4*)(q + i);
    float4 fv = *(const float4*)(v + i);
    float xq[4] = {fq.x, fq.y, fq.z, fq.w};
    float xv[4] = {fv.x, fv.y, fv.z, fv.w};
    __nv_bfloat16 qh[4], ql[4], vh[4], vl[4];
#pragma unroll
    for (int j = 0; j < 4; ++j) {
        qh[j] = __float2bfloat16(xq[j]);
        ql[j] = __float2bfloat16(xq[j] - __bfloat162float(qh[j]));
        vh[j] = __float2bfloat16(xv[j]);
        vl[j] = __float2bfloat16(xv[j] - __bfloat162float(vh[j]));
    }
    *(ull*)(g_qhi + i) = *(ull*)qh;
    *(ull*)(g_qlo + i) = *(ull*)ql;
    *(ull*)(g_vhi + i) = *(ull*)vh;
    *(ull*)(g_vlo + i) = *(ull*)vl;
}

// =====================================================================
// Pass 1 (unchanged, mma.sync bf16 split)
// =====================================================================
#define PITCH 272
#define TILE_B (128 * PITCH)
#define OFF_QLO   0
#define OFF_VBUF(x) (TILE_B + (x) * (2 * TILE_B))
#define OFF_RS    (TILE_B + 4 * TILE_B)
#define P1_SMEM   (OFF_RS + 128 * 2 * 4)

__device__ __forceinline__ void stage_tile(uint32_t dst,
                                           const __nv_bfloat16* src, int t) {
#pragma unroll
    for (int it = 0; it < 8; ++it) {
        int id = it * 256 + t;
        int r = id >> 4, c = id & 15;
        cp_async16(dst + r * PITCH + c * 16, src + r * 128 + c * 8);
    }
}

__global__ void __launch_bounds__(256, 1)
pass1_kernel(float* __restrict__ u) {
    extern __shared__ char sm[];
    const uint32_t smb = smem_u32(sm);
    float* rsbuf = (float*)(sm + OFF_RS);

    const int b  = blockIdx.y;
    const int i0 = blockIdx.x * 128;
    const int t  = threadIdx.x;
    const int w  = t >> 5;
    const int l  = t & 31;
    const int wm = w & 3;
    const int wn = w >> 2;

    const __nv_bfloat16* qhg = g_qhi + ((size_t)b * SEQ + i0) * DIM;
    const __nv_bfloat16* qlg = g_qlo + ((size_t)b * SEQ + i0) * DIM;
    const __nv_bfloat16* vhg = g_vhi + (size_t)b * SEQ * DIM;
    const __nv_bfloat16* vlg = g_vlo + (size_t)b * SEQ * DIM;

    const int rA = (l & 7) + ((l >> 3) & 1) * 8;
    const int cA = (l >> 4) * 8;
    const int rB = (l & 7) + (l >> 4) * 8;
    const int cB = ((l >> 3) & 1) * 8;

    stage_tile(smb + OFF_VBUF(0), qhg, t);
    stage_tile(smb + OFF_QLO,     qlg, t);
    CP_COMMIT();
    CP_WAIT0();
    __syncthreads();

    unsigned qh[2][8][4];
#pragma unroll
    for (int f = 0; f < 2; ++f)
#pragma unroll
        for (int k8 = 0; k8 < 8; ++k8) {
            uint32_t addr = smb + OFF_VBUF(0) +
                (wm * 32 + f * 16 + rA) * PITCH + (k8 * 16 + cA) * 2;
            ldm4(qh[f][k8], addr);
        }
    __syncthreads();

    uint32_t qloA[2];
#pragma unroll
    for (int f = 0; f < 2; ++f)
        qloA[f] = smb + OFF_QLO + (wm * 32 + f * 16 + rA) * PITCH + cA * 2;

    uint32_t bRow[4];
#pragma unroll
    for (int p = 0; p < 4; ++p)
        bRow[p] = (wn * 64 + p * 16 + rB) * PITCH + cB * 2;

    stage_tile(smb + OFF_VBUF(0),          vhg, t);
    stage_tile(smb + OFF_VBUF(0) + TILE_B, vlg, t);
    CP_COMMIT();
    stage_tile(smb + OFF_VBUF(1),          vhg + 128 * DIM, t);
    stage_tile(smb + OFF_VBUF(1) + TILE_B, vlg + 128 * DIM, t);
    CP_COMMIT();

    float* up[2];
#pragma unroll
    for (int f = 0; f < 2; ++f)
        up[f] = u + ((size_t)(b * SEQ + i0 + wm * 32 + f * 16 + (l >> 2))) * SEQ
                  + wn * 64 + (l & 3) * 2;

    float rs[2][2] = {{0.f, 0.f}, {0.f, 0.f}};
    const int NCHUNK = SEQ / 128;

    for (int c = 0; c < NCHUNK; ++c) {
        CP_WAIT1();
        __syncthreads();

        const uint32_t vh = smb + OFF_VBUF(c & 1);
        const uint32_t vl = vh + TILE_B;

        float acc[2][8][4];
#pragma unroll
        for (int f = 0; f < 2; ++f)
#pragma unroll
            for (int n = 0; n < 8; ++n)
#pragma unroll
                for (int x = 0; x < 4; ++x) acc[f][n][x] = 0.0f;

#pragma unroll
        for (int k8 = 0; k8 < 8; ++k8) {
            unsigned bh[4][4];
#pragma unroll
            for (int p = 0; p < 4; ++p)
                ldm4(bh[p], vh + bRow[p] + k8 * 32);
            unsigned al[2][4];
            ldm4(al[0], qloA[0] + k8 * 32);
            ldm4(al[1], qloA[1] + k8 * 32);
#pragma unroll
            for (int p = 0; p < 4; ++p)
#pragma unroll
                for (int h = 0; h < 2; ++h) {
                    const unsigned* bb = &bh[p][2 * h];
                    int n = 2 * p + h;
                    mma16816(acc[0][n], qh[0][k8], bb);
                    mma16816(acc[1][n], qh[1][k8], bb);
                    mma16816(acc[0][n], al[0], bb);
                    mma16816(acc[1][n], al[1], bb);
                }
            unsigned bl[4][4];
#pragma unroll
            for (int p = 0; p < 4; ++p)
                ldm4(bl[p], vl + bRow[p] + k8 * 32);
#pragma unroll
            for (int p = 0; p < 4; ++p)
#pragma unroll
                for (int h = 0; h < 2; ++h) {
                    const unsigned* bb = &bl[p][2 * h];
                    int n = 2 * p + h;
                    mma16816(acc[0][n], qh[0][k8], bb);
                    mma16816(acc[1][n], qh[1][k8], bb);
                }
        }

        __syncthreads();

        if (c + 2 < NCHUNK) {
            const uint32_t nb = smb + OFF_VBUF(c & 1);
            stage_tile(nb,          vhg + (size_t)(c + 2) * 128 * DIM, t);
            stage_tile(nb + TILE_B, vlg + (size_t)(c + 2) * 128 * DIM, t);
        }
        CP_COMMIT();

#pragma unroll
        for (int f = 0; f < 2; ++f) {
            float* row0 = up[f] + c * 128;
            float* row1 = row0 + 8 * SEQ;
#pragma unroll
            for (int n = 0; n < 8; ++n) {
                float e0 = __expf(acc[f][n][0] * INV_TEMP);
                float e1 = __expf(acc[f][n][1] * INV_TEMP);
                float e2 = __expf(acc[f][n][2] * INV_TEMP);
                float e3 = __expf(acc[f][n][3] * INV_TEMP);
                rs[f][0] += e0 + e1;
                rs[f][1] += e2 + e3;
                *(float2*)(row0 + n * 8) = make_float2(e0, e1);
                *(float2*)(row1 + n * 8) = make_float2(e2, e3);
            }
        }
    }

#pragma unroll
    for (int f = 0; f < 2; ++f)
#pragma unroll
        for (int h = 0; h < 2; ++h) {
            rs[f][h] += __shfl_xor_sync(0xffffffffu, rs[f][h], 1);
            rs[f][h] += __shfl_xor_sync(0xffffffffu, rs[f][h], 2);
        }
    if ((l & 3) == 0) {
#pragma unroll
        for (int f = 0; f < 2; ++f)
#pragma unroll
            for (int h = 0; h < 2; ++h) {
                int row = wm * 32 + f * 16 + h * 8 + (l >> 2);
                rsbuf[row * 2 + wn] = rs[f][h];
            }
    }
    __syncthreads();
    if (t < 128)
        g_inv_rs[b * SEQ + i0 + t] = 1.0f / (rsbuf[t * 2] + rsbuf[t * 2 + 1]);
}

// =====================================================================
// Pass 2 (mma.sync): attn = u * inv_rs (written back); out = attn^T @ v.
// CTA: 128 j x 128 d, 256 thr (8 warps: 4j x 2d), i in 32 chunks of 64.
// A = attn^T via ldmatrix.trans on [i][j] bf16 tiles (split hi/lo on the fly);
// B = v^T via ldmatrix.trans on [i][d] bf16 tiles (g_vhi/g_vlo).
// =====================================================================
#define P2_I    64
#define UPITCH  528                      // bytes per u-stage row (132 fp32)
#define U_BUF   (P2_I * UPITCH)          // 33792
#define APITCH  272
#define ATILE   (P2_I * APITCH)          // 17408
#define OFF_U(x)  ((x) * U_BUF)
#define OFF_AH(x) (2 * U_BUF + (x) * ATILE)
#define OFF_AL(x) (2 * U_BUF + 2 * ATILE + (x) * ATILE)
#define OFF_VH(x) (2 * U_BUF + 4 * ATILE + (x) * ATILE)
#define OFF_VL(x) (2 * U_BUF + 6 * ATILE + (x) * ATILE)
#define P2_SMEM   (2 * U_BUF + 8 * ATILE)   // 206848

__device__ __forceinline__ void stage_u64(uint32_t dst, const float* src, int t) {
#pragma unroll
    for (int it = 0; it < 8; ++it) {
        int id = it * 256 + t;
        int r = id >> 5, c = id & 31;
        cp_async16(dst + r * UPITCH + c * 16, src + (size_t)r * SEQ + c * 4);
    }
}
__device__ __forceinline__ void stage_v64(uint32_t dst,
                                          const __nv_bfloat16* src, int t) {
#pragma unroll
    for (int it = 0; it < 4; ++it) {
        int id = it * 256 + t;
        int r = id >> 4, c = id & 15;
        cp_async16(dst + r * APITCH + c * 16, src + r * 128 + c * 8);
    }
}

__global__ void __launch_bounds__(256, 1)
pass2_kernel(float* __restrict__ attn, float* __restrict__ out) {
    extern __shared__ char sm[];
    const uint32_t smb = smem_u32(sm);

    const int b  = blockIdx.y;
    const int j0 = blockIdx.x * 128;
    const int t  = threadIdx.x;
    const int w  = t >> 5;
    const int l  = t & 31;
    const int wm = w & 3;        // j-subtile (32 rows)
    const int wn = w >> 2;       // d-subtile (64 cols)

    float*       ab  = attn + (size_t)b * SEQ * SEQ;
    const __nv_bfloat16* vhg = g_vhi + (size_t)b * SEQ * DIM;
    const __nv_bfloat16* vlg = g_vlo + (size_t)b * SEQ * DIM;
    const float* irs = g_inv_rs + b * SEQ;
    float*       ob  = out + (size_t)b * SEQ * DIM;

    // trans-ldmatrix lane patterns ([k][x] storage)
    const int rAT = (l & 7) + ((l >> 4) & 1) * 8;   // A: k-row
    const int cAT = ((l >> 3) & 1) * 8;             // A: m(j)-col offset
    const int rBT = (l & 7) + ((l >> 3) & 1) * 8;   // B: k-row
    const int cBT = (l >> 4) * 8;                   // B: n(d)-col offset

    // convert-phase indices: thread handles u row i_loc, 8 j-quads
    const int i_loc = t >> 2;
    const int jq    = t & 3;

    // prologue: chunk 0 loads
    stage_u64(smb + OFF_U(0), ab + j0, t);
    stage_v64(smb + OFF_VH(0), vhg, t);
    stage_v64(smb + OFF_VL(0), vlg, t);
    CP_COMMIT();

    float acc[2][8][4];
#pragma unroll
    for (int f = 0; f < 2; ++f)
#pragma unroll
        for (int n = 0; n < 8; ++n)
#pragma unroll
            for (int x = 0; x < 4; ++x) acc[f][n][x] = 0.0f;

    const int NCHUNK = SEQ / P2_I;   // 32

    for (int c = 0; c < NCHUNK; ++c) {
        const int bu = c & 1;
        const int i0c = c * P2_I;

        CP_WAIT0();
        __syncthreads();   // chunk c data visible; prior phases complete

        // ---- convert: normalize u, STG attn, split to bf16 hi/lo ----
        {
            const float* urow = (const float*)(sm + OFF_U(bu) + i_loc * UPITCH);
            float* grow = ab + (size_t)(i0c + i_loc) * SEQ + j0;
            uint32_t ah = smb + OFF_AH(bu) + i_loc * APITCH;
            uint32_t al = smb + OFF_AL(bu) + i_loc * APITCH;
            const float s = __ldg(irs + i0c + i_loc);
#pragma unroll
            for (int it = 0; it < 8; ++it) {
                int j = jq * 4 + it * 16;
                float4 f4 = *(const float4*)(urow + j);
                f4.x *= s; f4.y *= s; f4.z *= s; f4.w *= s;
                *(float4*)(grow + j) = f4;
                __nv_bfloat162 h01 = __floats2bfloat162_rn(f4.x, f4.y);
                __nv_bfloat162 h23 = __floats2bfloat162_rn(f4.z, f4.w);
                __nv_bfloat162 l01 = __floats2bfloat162_rn(
                    f4.x - __bfloat162float(h01.x), f4.y - __bfloat162float(h01.y));
                __nv_bfloat162 l23 = __floats2bfloat162_rn(
                    f4.z - __bfloat162float(h23.x), f4.w - __bfloat162float(h23.y));
                unsigned hp[2] = {*(unsigned*)&h01, *(unsigned*)&h23};
                unsigned lp[2] = {*(unsigned*)&l01, *(unsigned*)&l23};
                asm volatile("st.shared.v2.b32 [%0], {%1, %2};"
                             :: "r"(ah + j * 2), "r"(hp[0]), "r"(hp[1]));
                asm volatile("st.shared.v2.b32 [%0], {%1, %2};"
                             :: "r"(al + j * 2), "r"(lp[0]), "r"(lp[1]));
            }
        }
        __syncthreads();   // tiles ready; u-stage[bu] free for reuse

        // ---- issue chunk c+1 loads (overlap with MMA below) ----
        if (c + 1 < NCHUNK) {
            const int nb = (c + 1) & 1;
            stage_u64(smb + OFF_U(nb), ab + (size_t)(i0c + P2_I) * SEQ + j0, t);
            stage_v64(smb + OFF_VH(nb), vhg + (size_t)(i0c + P2_I) * DIM, t);
            stage_v64(smb + OFF_VL(nb), vlg + (size_t)(i0c + P2_I) * DIM, t);
        }
        CP_COMMIT();

        // ---- MMA: acc[j,d] += attn^T(hi/lo) x v^T(hi/lo), 3 terms ----
        const uint32_t AH = smb + OFF_AH(bu);
        const uint32_t AL = smb + OFF_AL(bu);
        const uint32_t VH = smb + OFF_VH(bu);
        const uint32_t VL = smb + OFF_VL(bu);
#pragma unroll
        for (int k8 = 0; k8 < P2_I / 16; ++k8) {
            const uint32_t kro = (k8 * 16) * APITCH;
            unsigned ahf[2][4], alf[2][4];
#pragma unroll
            for (int f = 0; f < 2; ++f) {
                uint32_t coff = rAT * APITCH + (wm * 32 + f * 16 + cAT) * 2;
                ldm4t(ahf[f], AH + kro + coff);
                ldm4t(alf[f], AL + kro + coff);
            }
            unsigned bh[4][4];
#pragma unroll
            for (int p = 0; p < 4; ++p) {
                uint32_t coff = rBT * APITCH + (wn * 64 + p * 16 + cBT) * 2;
                ldm4t(bh[p], VH + kro + coff);
            }
#pragma unroll
            for (int p = 0; p < 4; ++p)
#pragma unroll
                for (int h = 0; h < 2; ++h) {
                    const unsigned* bb = &bh[p][2 * h];
                    int n = 2 * p + h;
                    mma16816(acc[0][n], ahf[0], bb);   // Ahi.Vhi
                    mma16816(acc[1][n], ahf[1], bb);
                    mma16816(acc[0][n], alf[0], bb);   // Alo.Vhi
                    mma16816(acc[1][n], alf[1], bb);
                }
            unsigned bl[4][4];
#pragma unroll
            for (int p = 0; p < 4; ++p) {
                uint32_t coff = rBT * APITCH + (wn * 64 + p * 16 + cBT) * 2;
                ldm4t(bl[p], VL + kro + coff);
            }
#pragma unroll
            for (int p = 0; p < 4; ++p)
#pragma unroll
                for (int h = 0; h < 2; ++h) {
                    const unsigned* bb = &bl[p][2 * h];
                    int n = 2 * p + h;
                    mma16816(acc[0][n], ahf[0], bb);   // Ahi.Vlo
                    mma16816(acc[1][n], ahf[1], bb);
                }
        }
    }

    // ---- store out[j,d] ----
#pragma unroll
    for (int f = 0; f < 2; ++f) {
        int jr = j0 + wm * 32 + f * 16 + (l >> 2);
        float* r0 = ob + (size_t)jr * DIM + wn * 64 + (l & 3) * 2;
#pragma unroll
        for (int n = 0; n < 8; ++n) {
            *(float2*)(r0 + n * 8)           = make_float2(acc[f][n][0], acc[f][n][1]);
            *(float2*)(r0 + n * 8 + 8 * DIM) = make_float2(acc[f][n][2], acc[f][n][3]);
        }
    }
}

// =====================================================================
extern "C" void kernel_launch(void* const* d_in, const int* in_sizes, int n_in,
                              void* d_out, int out_size) {
    const float* q = (const float*)d_in[0];
    // d_in[1] (k) unused by the reference
    const float* v = (const float*)d_in[2];

    float* out  = (float*)d_out;                      // [8,2048,128]
    float* attn = out + (size_t)BATCH * SEQ * DIM;    // [8,2048,2048]

    cudaFuncSetAttribute(pass1_kernel,
                         cudaFuncAttributeMaxDynamicSharedMemorySize, P1_SMEM);
    cudaFuncSetAttribute(pass2_kernel,
                         cudaFuncAttributeMaxDynamicSharedMemorySize, P2_SMEM);

    split_kernel<<<(BATCH * SEQ * DIM) / (256 * 4), 256>>>(q, v);

    dim3 g1(SEQ / 128, BATCH);
    pass1_kernel<<<g1, 256, P1_SMEM>>>(attn);

    dim3 g2(SEQ / 128, BATCH);
    pass2_kernel<<<g2, 256, P2_SMEM>>>(attn, out);
}